// round 2
// baseline (speedup 1.0000x reference)
#include <cuda_runtime.h>

#define FULL 0xffffffffu

// LISTA: 16 sequential stages of complex 8x8 affine + tiny conv pipeline over
// 64 batch columns. Thread = (batch column b, code position i). 4 blocks x 128
// threads: each block owns 16 columns; each warp owns 4 full columns so all
// cross-position traffic is warp shuffles (no __syncthreads in the main loop).

__global__ void __launch_bounds__(128, 1) lista_kernel(
    const float* __restrict__ y_real, const float* __restrict__ y_imag,
    const float* __restrict__ w1_real, const float* __restrict__ w1_imag,
    const float* __restrict__ w2_real, const float* __restrict__ w2_imag,
    const float* __restrict__ thr,
    const float* __restrict__ c1w, const float* __restrict__ c1b,
    const float* __restrict__ c2w, const float* __restrict__ c2b,
    float* __restrict__ out)
{
    __shared__ float s_w1r[1024], s_w1i[1024], s_w2r[1024], s_w2i[1024];
    __shared__ float s_c1w[144], s_c1b[48], s_c2w[144], s_c2b[16], s_thr[16];

    const int tid  = threadIdx.x;          // 0..127
    const int lane = tid & 31;
    const int i    = tid & 7;              // code position 0..7
    const int b    = (int)blockIdx.x * 16 + (tid >> 3);  // batch column 0..63

    // ---- cooperative weight staging (vectorized where possible) ----
    {
        const float4* g;
        float4* s;
        g = (const float4*)w1_real; s = (float4*)s_w1r;
        #pragma unroll
        for (int k = tid; k < 256; k += 128) s[k] = g[k];
        g = (const float4*)w1_imag; s = (float4*)s_w1i;
        #pragma unroll
        for (int k = tid; k < 256; k += 128) s[k] = g[k];
        g = (const float4*)w2_real; s = (float4*)s_w2r;
        #pragma unroll
        for (int k = tid; k < 256; k += 128) s[k] = g[k];
        g = (const float4*)w2_imag; s = (float4*)s_w2i;
        #pragma unroll
        for (int k = tid; k < 256; k += 128) s[k] = g[k];
    }
    // 144 > blockDim(128): MUST stride (this was the R1 correctness bug)
    #pragma unroll
    for (int k = tid; k < 144; k += 128) { s_c1w[k] = c1w[k]; s_c2w[k] = c2w[k]; }
    if (tid < 48)  { s_c1b[tid] = c1b[tid]; }
    if (tid < 16)  { s_c2b[tid] = c2b[tid]; s_thr[tid] = thr[tid]; }

    // ---- per-thread y column (broadcast-friendly loads) ----
    float yr[8], yi[8];
    #pragma unroll
    for (int j = 0; j < 8; j++) {
        yr[j] = y_real[j * 64 + b];
        yi[j] = y_imag[j * 64 + b];
    }

    __syncthreads();

    const unsigned gbase = (unsigned)(lane & 24);  // base lane of this column's 8-group
    const int lm1 = (lane + 31) & 31;              // lane-1 (wrapped; masked at i==0)
    const int lp1 = (lane + 1)  & 31;              // lane+1 (wrapped; masked at i==7)

    // ---- init: x = soft(W1[0] y, thr[0]) ----
    float xr, xi;
    {
        const float* pr = &s_w1r[i * 8];
        const float* pi = &s_w1i[i * 8];
        float ar = 0.f, ai = 0.f;
        #pragma unroll
        for (int j = 0; j < 8; j++) {
            const float vr = pr[j], vi = pi[j];
            ar = fmaf(vr, yr[j], ar); ar = fmaf(-vi, yi[j], ar);
            ai = fmaf(vr, yi[j], ai); ai = fmaf( vi, yr[j], ai);
        }
        const float t0 = s_thr[0];
        xr = fmaxf(ar - t0, 0.f) + fminf(ar + t0, 0.f);
        xi = fmaxf(ai - t0, 0.f) + fminf(ai + t0, 0.f);
    }

    // ---- 16 sequential stages ----
    for (int s = 0; s < 16; s++) {
        // broadcast the full x vector of this column within the warp
        float xrj[8], xij[8];
        #pragma unroll
        for (int j = 0; j < 8; j++) {
            xrj[j] = __shfl_sync(FULL, xr, gbase + j);
            xij[j] = __shfl_sync(FULL, xi, gbase + j);
        }

        // z = W2 x + W1 y (complex), row i
        const float* w2r = &s_w2r[(s * 8 + i) * 8];
        const float* w2i = &s_w2i[(s * 8 + i) * 8];
        const float* w1r = &s_w1r[(s * 8 + i) * 8];
        const float* w1i = &s_w1i[(s * 8 + i) * 8];
        float zr0 = 0.f, zi0 = 0.f, zr1 = 0.f, zi1 = 0.f;
        #pragma unroll
        for (int j = 0; j < 8; j += 2) {
            {
                const float ar = w2r[j], bi2 = w2i[j], vr = w1r[j], vi = w1i[j];
                zr0 = fmaf(ar, xrj[j], zr0); zr0 = fmaf(-bi2, xij[j], zr0);
                zr0 = fmaf(vr, yr[j],  zr0); zr0 = fmaf(-vi,  yi[j],  zr0);
                zi0 = fmaf(ar, xij[j], zi0); zi0 = fmaf( bi2, xrj[j], zi0);
                zi0 = fmaf(vr, yi[j],  zi0); zi0 = fmaf( vi,  yr[j],  zi0);
            }
            {
                const int j1 = j + 1;
                const float ar = w2r[j1], bi2 = w2i[j1], vr = w1r[j1], vi = w1i[j1];
                zr1 = fmaf(ar, xrj[j1], zr1); zr1 = fmaf(-bi2, xij[j1], zr1);
                zr1 = fmaf(vr, yr[j1],  zr1); zr1 = fmaf(-vi,  yi[j1],  zr1);
                zi1 = fmaf(ar, xij[j1], zi1); zi1 = fmaf( bi2, xrj[j1], zi1);
                zi1 = fmaf(vr, yi[j1],  zi1); zi1 = fmaf( vi,  yr[j1],  zi1);
            }
        }
        const float zr = zr0 + zr1;
        const float zi = zi0 + zi1;

        // neighbor z values for conv1 (3-tap, pad=1)
        float zrm = __shfl_sync(FULL, zr, lm1);
        float zim = __shfl_sync(FULL, zi, lm1);
        float zrp = __shfl_sync(FULL, zr, lp1);
        float zip = __shfl_sync(FULL, zi, lp1);
        if (i == 0) { zrm = 0.f; zim = 0.f; }
        if (i == 7) { zrp = 0.f; zip = 0.f; }

        // conv1 + soft threshold, 3 channels
        const float t = s_thr[s];
        float sr[3], si[3];
        #pragma unroll
        for (int ch = 0; ch < 3; ch++) {
            const float w0 = s_c1w[s * 9 + ch * 3 + 0];
            const float w1 = s_c1w[s * 9 + ch * 3 + 1];
            const float w2 = s_c1w[s * 9 + ch * 3 + 2];
            const float bb = s_c1b[s * 3 + ch];
            float cr = bb;
            cr = fmaf(w0, zrm, cr); cr = fmaf(w1, zr, cr); cr = fmaf(w2, zrp, cr);
            float ci = bb;
            ci = fmaf(w0, zim, ci); ci = fmaf(w1, zi, ci); ci = fmaf(w2, zip, ci);
            sr[ch] = fmaxf(cr - t, 0.f) + fminf(cr + t, 0.f);
            si[ch] = fmaxf(ci - t, 0.f) + fminf(ci + t, 0.f);
        }

        // conv2 (3ch -> 1), neighbor taps via shuffle
        float nr = s_c2b[s], ni = s_c2b[s];
        #pragma unroll
        for (int ch = 0; ch < 3; ch++) {
            float srm = __shfl_sync(FULL, sr[ch], lm1);
            float sim = __shfl_sync(FULL, si[ch], lm1);
            float srp = __shfl_sync(FULL, sr[ch], lp1);
            float sip = __shfl_sync(FULL, si[ch], lp1);
            if (i == 0) { srm = 0.f; sim = 0.f; }
            if (i == 7) { srp = 0.f; sip = 0.f; }
            const float w0 = s_c2w[s * 9 + ch * 3 + 0];
            const float w1 = s_c2w[s * 9 + ch * 3 + 1];
            const float w2 = s_c2w[s * 9 + ch * 3 + 2];
            nr = fmaf(w0, srm, nr); nr = fmaf(w1, sr[ch], nr); nr = fmaf(w2, srp, nr);
            ni = fmaf(w0, sim, ni); ni = fmaf(w1, si[ch], ni); ni = fmaf(w2, sip, ni);
        }
        xr = nr;
        xi = ni;
    }

    // output: x_r (8,64) then x_i (8,64), row-major
    out[i * 64 + b]       = xr;
    out[512 + i * 64 + b] = xi;
}

extern "C" void kernel_launch(void* const* d_in, const int* in_sizes, int n_in,
                              void* d_out, int out_size) {
    (void)in_sizes; (void)n_in; (void)out_size;
    const float* y_real  = (const float*)d_in[0];
    const float* y_imag  = (const float*)d_in[1];
    const float* w1_real = (const float*)d_in[2];
    const float* w1_imag = (const float*)d_in[3];
    const float* w2_real = (const float*)d_in[4];
    const float* w2_imag = (const float*)d_in[5];
    const float* thr     = (const float*)d_in[6];
    const float* c1w     = (const float*)d_in[7];
    const float* c1b     = (const float*)d_in[8];
    const float* c2w     = (const float*)d_in[9];
    const float* c2b     = (const float*)d_in[10];
    float* out = (float*)d_out;

    lista_kernel<<<4, 128>>>(y_real, y_imag, w1_real, w1_imag,
                             w2_real, w2_imag, thr, c1w, c1b, c2w, c2b, out);
}

// round 5
// speedup vs baseline: 1.2399x; 1.2399x over previous
#include <cuda_runtime.h>

#define FULL 0xffffffffu

// LISTA, latency-optimized: warp = one batch column.
// Lane layout: lane = h*16 + c*8 + i  (i = code position 0..7,
// c = component 0:real 1:imag, h = j-half of the 8-wide dot product).
// Per-stage chain: 8 shfl (x broadcast) -> 8 FMA (half dot product)
// -> 1 shfl_xor reduce -> 4 shfl (z neighbors +-1,+-2) -> local conv1 at
// 3 positions -> conv2 (no third shuffle wave). W1[s]@y HALF-biases are
// precomputed off-chain into registers (the xor-16 stage reduce completes
// them together with the W2 x half-dots). 16 blocks x 128 threads.

__global__ void __launch_bounds__(128, 1) lista_kernel(
    const float* __restrict__ y_real, const float* __restrict__ y_imag,
    const float* __restrict__ w1_real, const float* __restrict__ w1_imag,
    const float* __restrict__ w2_real, const float* __restrict__ w2_imag,
    const float* __restrict__ thr,
    const float* __restrict__ c1w, const float* __restrict__ c1b,
    const float* __restrict__ c2w, const float* __restrict__ c2b,
    float* __restrict__ out)
{
    // conv params staged into shared, padded + aligned for LDS.128
    __shared__ __align__(16) float s_c1w[16 * 12];   // 9 used + 3 pad per stage
    __shared__ __align__(16) float s_c1b[16 * 4];    // 3 used + 1 pad
    __shared__ __align__(16) float s_c2w[16 * 12];
    __shared__ __align__(16) float s_misc[16 * 2];   // {c2b[s], thr[s]}

    const int tid  = threadIdx.x;
    const int lane = tid & 31;
    const int i    = lane & 7;
    const int c    = (lane >> 3) & 1;
    const int h    = lane >> 4;
    const int b    = (int)blockIdx.x * 4 + (tid >> 5);   // batch column
    const float sgn = c ? 1.f : -1.f;   // zr uses -w_i*x_i ; zi uses +w_i*x_r

    // ---- one-time staging of conv params (padded, aligned) ----
    for (int k = tid; k < 192; k += 128) {
        int s = k / 12, r = k - s * 12;
        s_c1w[k] = (r < 9) ? c1w[s * 9 + r] : 0.f;
        s_c2w[k] = (r < 9) ? c2w[s * 9 + r] : 0.f;
    }
    if (tid < 64) {
        int s = tid >> 2, r = tid & 3;
        s_c1b[tid] = (r < 3) ? c1b[s * 3 + r] : 0.f;
    }
    if (tid < 32) {
        int s = tid >> 1;
        s_misc[tid] = (tid & 1) ? thr[s] : c2b[s];
    }

    // ---- y slice for this thread's j-half (own comp + signed opposite) ----
    float yc[4], yos[4];
    {
        const float* yc_ptr = c ? y_imag : y_real;
        const float* yo_ptr = c ? y_real : y_imag;
        #pragma unroll
        for (int j4 = 0; j4 < 4; j4++) {
            int j = h * 4 + j4;
            yc[j4]  = yc_ptr[j * 64 + b];
            yos[j4] = sgn * yo_ptr[j * 64 + b];
        }
    }

    // ---- precompute all 16 stage HALF-biases (W1[s] y)_{i,c}, this j-half.
    // NOT reduced here: the stage loop's xor-16 reduce completes the sum
    // (R4 bug was reducing here AND seeding both halves -> bias x2).
    float bias[16];
    #pragma unroll
    for (int s = 0; s < 16; s++) {
        const float4 wr = *(const float4*)(w1_real + s * 64 + i * 8 + h * 4);
        const float4 wi = *(const float4*)(w1_imag + s * 64 + i * 8 + h * 4);
        float a = 0.f;
        a = fmaf(wr.x, yc[0], a); a = fmaf(wi.x, yos[0], a);
        a = fmaf(wr.y, yc[1], a); a = fmaf(wi.y, yos[1], a);
        a = fmaf(wr.z, yc[2], a); a = fmaf(wi.z, yos[2], a);
        a = fmaf(wr.w, yc[3], a); a = fmaf(wi.w, yos[3], a);
        bias[s] = a;                       // half-sum only
    }

    __syncthreads();

    // ---- init: x = soft(full bias[0], thr[0]) ----
    float x;
    {
        const float b0 = bias[0] + __shfl_xor_sync(FULL, bias[0], 16);
        const float t0 = s_misc[1];
        x = fmaxf(b0 - t0, 0.f) + fminf(b0 + t0, 0.f);
    }

    const int src_c = (c << 3);        // lanes holding own-comp x_j
    const int src_o = ((c ^ 1) << 3);  // lanes holding opposite-comp x_j
    const int nbase = lane & 24;       // keep (c,h) bits for neighbor shfl

    // ---- 16 sequential stages (fully unrolled) ----
    #pragma unroll
    for (int s = 0; s < 16; s++) {
        // broadcast x for this thread's j-half
        float xc[4], xos[4];
        #pragma unroll
        for (int j4 = 0; j4 < 4; j4++) {
            int j = h * 4 + j4;
            xc[j4]  = __shfl_sync(FULL, x, src_c + j);
            xos[j4] = sgn * __shfl_sync(FULL, x, src_o + j);
        }

        // half dot: a = half-bias + sum_j w2r*xc + w2i*(sgn*xo)
        const float4 wr = *(const float4*)(w2_real + s * 64 + i * 8 + h * 4);
        const float4 wi = *(const float4*)(w2_imag + s * 64 + i * 8 + h * 4);
        float a = bias[s];
        a = fmaf(wr.x, xc[0], a); a = fmaf(wi.x, xos[0], a);
        a = fmaf(wr.y, xc[1], a); a = fmaf(wi.y, xos[1], a);
        a = fmaf(wr.z, xc[2], a); a = fmaf(wi.z, xos[2], a);
        a = fmaf(wr.w, xc[3], a); a = fmaf(wi.w, xos[3], a);
        float z = a + __shfl_xor_sync(FULL, a, 16);   // completes bias + dot

        // z neighbors at +-1, +-2 (same component, zero-padded)
        float zv[5];
        zv[2] = z;
        float zm2 = __shfl_sync(FULL, z, nbase | ((i - 2) & 7));
        float zm1 = __shfl_sync(FULL, z, nbase | ((i - 1) & 7));
        float zp1 = __shfl_sync(FULL, z, nbase | ((i + 1) & 7));
        float zp2 = __shfl_sync(FULL, z, nbase | ((i + 2) & 7));
        zv[0] = (i >= 2) ? zm2 : 0.f;
        zv[1] = (i >= 1) ? zm1 : 0.f;
        zv[3] = (i <= 6) ? zp1 : 0.f;
        zv[4] = (i <= 5) ? zp2 : 0.f;

        // conv params (shared, broadcast LDS.128)
        const float4 wa  = *(const float4*)(s_c1w + s * 12);
        const float4 wb  = *(const float4*)(s_c1w + s * 12 + 4);
        const float4 wcv = *(const float4*)(s_c1w + s * 12 + 8);
        const float4 b1  = *(const float4*)(s_c1b + s * 4);
        const float4 va  = *(const float4*)(s_c2w + s * 12);
        const float4 vb  = *(const float4*)(s_c2w + s * 12 + 4);
        const float4 vc  = *(const float4*)(s_c2w + s * 12 + 8);
        const float  cb2 = s_misc[s * 2];
        const float  t   = s_misc[s * 2 + 1];

        const float k1[3][3] = {{wa.x, wa.y, wa.z},
                                {wa.w, wb.x, wb.y},
                                {wb.z, wb.w, wcv.x}};
        const float k2[3][3] = {{va.x, va.y, va.z},
                                {va.w, vb.x, vb.y},
                                {vb.z, vb.w, vc.x}};
        const float bb1[3] = {b1.x, b1.y, b1.z};

        // conv1 + soft at positions i-1, i, i+1 computed locally,
        // then conv2 at i — no third shuffle wave.
        float o = cb2;
        #pragma unroll
        for (int p3 = 0; p3 < 3; p3++) {                 // pos = i-1+p3
            const bool valid = (p3 == 1) || ((p3 == 0) ? (i > 0) : (i < 7));
            #pragma unroll
            for (int ch = 0; ch < 3; ch++) {
                float v = bb1[ch];
                v = fmaf(k1[ch][0], zv[p3],     v);
                v = fmaf(k1[ch][1], zv[p3 + 1], v);
                v = fmaf(k1[ch][2], zv[p3 + 2], v);
                float st = fmaxf(v - t, 0.f) + fminf(v + t, 0.f);
                st = valid ? st : 0.f;                   // conv2 zero-padding
                o = fmaf(k2[ch][p3], st, o);
            }
        }
        x = o;
    }

    // out: x_r (8,64) then x_i (8,64); h=0 lanes write
    if (h == 0) out[c * 512 + i * 64 + b] = x;
}

extern "C" void kernel_launch(void* const* d_in, const int* in_sizes, int n_in,
                              void* d_out, int out_size) {
    (void)in_sizes; (void)n_in; (void)out_size;
    const float* y_real  = (const float*)d_in[0];
    const float* y_imag  = (const float*)d_in[1];
    const float* w1_real = (const float*)d_in[2];
    const float* w1_imag = (const float*)d_in[3];
    const float* w2_real = (const float*)d_in[4];
    const float* w2_imag = (const float*)d_in[5];
    const float* thr     = (const float*)d_in[6];
    const float* c1w     = (const float*)d_in[7];
    const float* c1b     = (const float*)d_in[8];
    const float* c2w     = (const float*)d_in[9];
    const float* c2b     = (const float*)d_in[10];
    float* out = (float*)d_out;

    lista_kernel<<<16, 128>>>(y_real, y_imag, w1_real, w1_imag,
                              w2_real, w2_imag, thr, c1w, c1b, c2w, c2b, out);
}